// round 3
// baseline (speedup 1.0000x reference)
#include <cuda_runtime.h>

#define NN 16384   // nodes
#define NE 4096    // edges
#define DD 256     // feature dim

// ---------------- scratch (device globals; no allocation allowed) ----------------
__device__ float g_xw1[NN * DD];   // x @ w1                       16 MB
__device__ float g_fe [NE * DD];   // edge features f = leaky(e^T @ xw1)   4 MB
__device__ float g_g  [NE * DD];   // g = f @ w2                    4 MB
__device__ float g_s1 [NN];        // exp(8*tanh(f_n/8)) node weight
__device__ float g_r  [NN];        // leaky(xw1) @ a22
__device__ float g_c  [NE];        // leaky(g) @ a21

__device__ __forceinline__ float lrelu(float v) { return v > 0.0f ? v : 0.1f * v; }

// exp(8*tanh(z/8)) using tanh(y) = 1 - 2/(e^{2y}+1) (exact identity, safe at +-inf)
__device__ __forceinline__ float softexp8(float z) {
    float v = __expf(z * 0.25f);                 // e^{2*(z/8)}
    float t = 1.0f - __fdividef(2.0f, v + 1.0f); // tanh(z/8); v=inf -> t=1, v=0 -> t=-1
    return __expf(8.0f * t);
}

// =====================================================================
// Generic [M,256] @ [256,256] GEMM, 32x128 tile, 128 threads, 4x8 micro
// sel==0: C = g_xw1, A = param     (xw1 = x @ w1)
// sel==1: C = g_g,   A = g_fe     (g = f_edge @ w2)
// =====================================================================
__global__ void __launch_bounds__(128) k_mm(const float* __restrict__ Ain,
                                            const float* __restrict__ B,
                                            int sel) {
    __shared__ float As[32][33];
    __shared__ float Bs[32][132];
    const float* A = sel ? g_fe : Ain;
    float*       C = sel ? g_g  : g_xw1;

    const int tid = threadIdx.x;
    const int la = tid & 31, wg = tid >> 5;   // load mapping
    const int tx = tid & 15, ty = tid >> 4;   // compute mapping
    const int r0 = ty * 4, c0 = tx * 8;
    const int m0 = blockIdx.x * 32;
    const int dbase = blockIdx.y * 128;

    float acc[4][8];
#pragma unroll
    for (int i = 0; i < 4; i++)
#pragma unroll
        for (int j = 0; j < 8; j++) acc[i][j] = 0.0f;

    float ra[8]; float4 rb[8];

    auto load = [&](int kb) {
#pragma unroll
        for (int j = 0; j < 8; j++)
            ra[j] = A[(size_t)(m0 + wg + 4 * j) * DD + kb + la];
#pragma unroll
        for (int j = 0; j < 8; j++)
            rb[j] = *reinterpret_cast<const float4*>(
                &B[(size_t)(kb + wg + 4 * j) * DD + dbase + la * 4]);
    };
    auto store = [&]() {
#pragma unroll
        for (int j = 0; j < 8; j++) As[wg + 4 * j][la] = ra[j];
#pragma unroll
        for (int j = 0; j < 8; j++)
            *reinterpret_cast<float4*>(&Bs[wg + 4 * j][la * 4]) = rb[j];
    };

    load(0); store(); __syncthreads();
    const int KT = DD / 32;
    for (int kt = 0; kt < KT; kt++) {
        if (kt + 1 < KT) load((kt + 1) * 32);
#pragma unroll 8
        for (int k = 0; k < 32; k++) {
            float a[4];
#pragma unroll
            for (int i = 0; i < 4; i++) a[i] = As[r0 + i][k];
            float4 b0 = *reinterpret_cast<const float4*>(&Bs[k][c0]);
            float4 b1 = *reinterpret_cast<const float4*>(&Bs[k][c0 + 4]);
            float b[8] = {b0.x, b0.y, b0.z, b0.w, b1.x, b1.y, b1.z, b1.w};
#pragma unroll
            for (int i = 0; i < 4; i++)
#pragma unroll
                for (int j = 0; j < 8; j++) acc[i][j] += a[i] * b[j];
        }
        __syncthreads();
        if (kt + 1 < KT) { store(); __syncthreads(); }
    }
#pragma unroll
    for (int i = 0; i < 4; i++) {
        float* o = &C[(size_t)(m0 + r0 + i) * DD + dbase + c0];
        *reinterpret_cast<float4*>(o)     = make_float4(acc[i][0], acc[i][1], acc[i][2], acc[i][3]);
        *reinterpret_cast<float4*>(o + 4) = make_float4(acc[i][4], acc[i][5], acc[i][6], acc[i][7]);
    }
}

// =====================================================================
// Per-node: f = leaky(xw1)@a1, r = leaky(xw1)@a22, s1 = exp(8 tanh(f/8))
// one warp per row
// =====================================================================
__global__ void k_node(const float* __restrict__ a1, const float* __restrict__ a22) {
    const int lane = threadIdx.x & 31;
    const int row = blockIdx.x * 8 + (threadIdx.x >> 5);
    const float* rp = &g_xw1[(size_t)row * DD];
    float f = 0.0f, r = 0.0f;
#pragma unroll
    for (int j = 0; j < 8; j++) {
        int d = lane + 32 * j;
        float v = lrelu(rp[d]);
        f += v * __ldg(&a1[d]);
        r += v * __ldg(&a22[d]);
    }
#pragma unroll
    for (int o = 16; o > 0; o >>= 1) {
        f += __shfl_down_sync(0xffffffffu, f, o);
        r += __shfl_down_sync(0xffffffffu, r, o);
    }
    if (lane == 0) { g_s1[row] = softexp8(f); g_r[row] = r; }
}

// =====================================================================
// Per-edge: c = leaky(g)@a21, one warp per row
// =====================================================================
__global__ void k_cedge(const float* __restrict__ a21) {
    const int lane = threadIdx.x & 31;
    const int row = blockIdx.x * 8 + (threadIdx.x >> 5);
    const float* rp = &g_g[(size_t)row * DD];
    float c = 0.0f;
#pragma unroll
    for (int j = 0; j < 8; j++) {
        int d = lane + 32 * j;
        c += lrelu(rp[d]) * __ldg(&a21[d]);
    }
#pragma unroll
    for (int o = 16; o > 0; o >>= 1) c += __shfl_down_sync(0xffffffffu, c, o);
    if (lane == 0) g_c[row] = c;
}

// =====================================================================
// Big GEMM 1 (fused): G[e,d] = sum_n (H[n,e]*s1[n]) * xw1[n,d]
//                     colsum[e] = sum_n H[n,e]*s1[n]
//                     g_fe = leaky(G / colsum)
// tiles: 32 edges x 128 d, K over N (512 tiles)
// =====================================================================
__global__ void __launch_bounds__(128) k_edge(const float* __restrict__ H) {
    __shared__ float As[32][33];   // As[e_local][n_local] (transposed, pre-scaled)
    __shared__ float Bs[32][132];  // Bs[n_local][d]
    const int tid = threadIdx.x;
    const int la = tid & 31, wg = tid >> 5;
    const int tx = tid & 15, ty = tid >> 4;
    const int r0 = ty * 4, c0 = tx * 8;
    const int e0 = blockIdx.x * 32;
    const int dbase = blockIdx.y * 128;

    float acc[4][8];
#pragma unroll
    for (int i = 0; i < 4; i++)
#pragma unroll
        for (int j = 0; j < 8; j++) acc[i][j] = 0.0f;
    float cs[4] = {0.0f, 0.0f, 0.0f, 0.0f};

    float ra[8], rs1[8]; float4 rb[8];

    auto load = [&](int n0) {
#pragma unroll
        for (int j = 0; j < 8; j++) {
            int n = n0 + wg + 4 * j;
            ra[j]  = H[(size_t)n * NE + e0 + la];
            rs1[j] = __ldg(&g_s1[n]);
            rb[j]  = *reinterpret_cast<const float4*>(
                &g_xw1[(size_t)n * DD + dbase + la * 4]);
        }
    };
    auto store = [&]() {
#pragma unroll
        for (int j = 0; j < 8; j++) As[la][wg + 4 * j] = ra[j] * rs1[j];
#pragma unroll
        for (int j = 0; j < 8; j++)
            *reinterpret_cast<float4*>(&Bs[wg + 4 * j][la * 4]) = rb[j];
    };

    load(0); store(); __syncthreads();
    const int KT = NN / 32;
    for (int kt = 0; kt < KT; kt++) {
        if (kt + 1 < KT) load((kt + 1) * 32);
#pragma unroll 8
        for (int k = 0; k < 32; k++) {
            float a[4];
#pragma unroll
            for (int i = 0; i < 4; i++) { a[i] = As[r0 + i][k]; cs[i] += a[i]; }
            float4 b0 = *reinterpret_cast<const float4*>(&Bs[k][c0]);
            float4 b1 = *reinterpret_cast<const float4*>(&Bs[k][c0 + 4]);
            float b[8] = {b0.x, b0.y, b0.z, b0.w, b1.x, b1.y, b1.z, b1.w};
#pragma unroll
            for (int i = 0; i < 4; i++)
#pragma unroll
                for (int j = 0; j < 8; j++) acc[i][j] += a[i] * b[j];
        }
        __syncthreads();
        if (kt + 1 < KT) { store(); __syncthreads(); }
    }
#pragma unroll
    for (int i = 0; i < 4; i++) {
        float inv = 1.0f / cs[i];
        float* o = &g_fe[(size_t)(e0 + r0 + i) * DD + dbase + c0];
        float4 v0 = make_float4(lrelu(acc[i][0] * inv), lrelu(acc[i][1] * inv),
                                lrelu(acc[i][2] * inv), lrelu(acc[i][3] * inv));
        float4 v1 = make_float4(lrelu(acc[i][4] * inv), lrelu(acc[i][5] * inv),
                                lrelu(acc[i][6] * inv), lrelu(acc[i][7] * inv));
        *reinterpret_cast<float4*>(o)     = v0;
        *reinterpret_cast<float4*>(o + 4) = v1;
    }
}

// =====================================================================
// Big GEMM 2 (fused): w(n,e) = H[n,e]*exp(8 tanh((c_e + r_n)/8))
//                     out[n,d] = leaky( (sum_e w*g[e,d]) / (sum_e w) )
// tiles: 32 nodes x 128 d, K over E (128 tiles)
// =====================================================================
__global__ void __launch_bounds__(128) k_out(const float* __restrict__ H,
                                             float* __restrict__ out) {
    __shared__ float As[32][33];   // As[n_local][e_local] = H * s2
    __shared__ float Bs[32][132];  // Bs[e_local][d] = g
    __shared__ float rsh[32];
    const int tid = threadIdx.x;
    const int la = tid & 31, wg = tid >> 5;
    const int tx = tid & 15, ty = tid >> 4;
    const int r0 = ty * 4, c0 = tx * 8;
    const int m0 = blockIdx.x * 32;
    const int dbase = blockIdx.y * 128;

    if (tid < 32) rsh[tid] = g_r[m0 + tid];

    float acc[4][8];
#pragma unroll
    for (int i = 0; i < 4; i++)
#pragma unroll
        for (int j = 0; j < 8; j++) acc[i][j] = 0.0f;
    float rs[4] = {0.0f, 0.0f, 0.0f, 0.0f};

    float ra[8]; float4 rb[8]; float cv = 0.0f;

    auto load = [&](int e0) {
        cv = __ldg(&g_c[e0 + la]);   // each thread touches a single edge column
#pragma unroll
        for (int j = 0; j < 8; j++)
            ra[j] = H[(size_t)(m0 + wg + 4 * j) * NE + e0 + la];
#pragma unroll
        for (int j = 0; j < 8; j++)
            rb[j] = *reinterpret_cast<const float4*>(
                &g_g[(size_t)(e0 + wg + 4 * j) * DD + dbase + la * 4]);
    };
    auto store = [&]() {
#pragma unroll
        for (int j = 0; j < 8; j++) {
            float av = 0.0f;
            if (ra[j] != 0.0f) av = softexp8(cv + rsh[wg + 4 * j]);  // H is 0/1
            As[wg + 4 * j][la] = av;
        }
#pragma unroll
        for (int j = 0; j < 8; j++)
            *reinterpret_cast<float4*>(&Bs[wg + 4 * j][la * 4]) = rb[j];
    };

    load(0);
    __syncthreads();   // rsh visible before store() reads it
    store(); __syncthreads();
    const int KT = NE / 32;
    for (int kt = 0; kt < KT; kt++) {
        if (kt + 1 < KT) load((kt + 1) * 32);
#pragma unroll 8
        for (int k = 0; k < 32; k++) {
            float a[4];
#pragma unroll
            for (int i = 0; i < 4; i++) { a[i] = As[r0 + i][k]; rs[i] += a[i]; }
            float4 b0 = *reinterpret_cast<const float4*>(&Bs[k][c0]);
            float4 b1 = *reinterpret_cast<const float4*>(&Bs[k][c0 + 4]);
            float b[8] = {b0.x, b0.y, b0.z, b0.w, b1.x, b1.y, b1.z, b1.w};
#pragma unroll
            for (int i = 0; i < 4; i++)
#pragma unroll
                for (int j = 0; j < 8; j++) acc[i][j] += a[i] * b[j];
        }
        __syncthreads();
        if (kt + 1 < KT) { store(); __syncthreads(); }
    }
#pragma unroll
    for (int i = 0; i < 4; i++) {
        float inv = 1.0f / rs[i];
        float* o = &out[(size_t)(m0 + r0 + i) * DD + dbase + c0];
        float4 v0 = make_float4(lrelu(acc[i][0] * inv), lrelu(acc[i][1] * inv),
                                lrelu(acc[i][2] * inv), lrelu(acc[i][3] * inv));
        float4 v1 = make_float4(lrelu(acc[i][4] * inv), lrelu(acc[i][5] * inv),
                                lrelu(acc[i][6] * inv), lrelu(acc[i][7] * inv));
        *reinterpret_cast<float4*>(o)     = v0;
        *reinterpret_cast<float4*>(o + 4) = v1;
    }
}

// =====================================================================
extern "C" void kernel_launch(void* const* d_in, const int* in_sizes, int n_in,
                              void* d_out, int out_size) {
    const float* x   = (const float*)d_in[0];   // [N, 256]
    const float* H   = (const float*)d_in[1];   // [N, E]
    const float* w1  = (const float*)d_in[2];   // [256, 256]
    const float* w2  = (const float*)d_in[3];   // [256, 256]
    const float* a1  = (const float*)d_in[4];   // [256]
    const float* a21 = (const float*)d_in[5];   // [256]
    const float* a22 = (const float*)d_in[6];   // [256]
    float* out = (float*)d_out;                 // [N, 256]

    // 1) xw1 = x @ w1
    k_mm<<<dim3(NN / 32, 2), 128>>>(x, w1, 0);
    // 2) per-node stats: s1, r
    k_node<<<NN / 8, 256>>>(a1, a22);
    // 3) edge features: f_edge = leaky((H*s1)^T @ xw1 / colsum)
    k_edge<<<dim3(NE / 32, 2), 128>>>(H);
    // 4) g = f_edge @ w2
    k_mm<<<dim3(NE / 32, 2), 128>>>(nullptr, w2, 1);
    // 5) per-edge stats: c
    k_cedge<<<NE / 8, 256>>>(a21);
    // 6) out = leaky(normalize(H*s2) @ g)
    k_out<<<dim3(NN / 32, 2), 128>>>(H, out);
}